// round 2
// baseline (speedup 1.0000x reference)
#include <cuda_runtime.h>

// MorphologicalDilation: out[b,ho,wo,f] = max_{k in 0..8} ( x[b, ho+ki, wo+kj, 0] + w[k, f] )
// x: (16, 256, 256, 1) f32   w: (1,1,1,9,32) f32   out: (16, 254, 254, 32) f32
//
// Memory-bound by the 132 MB output store. Layout: 8 lanes per spatial
// position, each lane holds 4 consecutive filters -> float4 STG, fully
// coalesced along the contiguous filter dimension.

#define H_IN   256
#define W_IN   256
#define KH     3
#define KW     3
#define NF     32
#define H_OUT  (H_IN - KH + 1)   // 254
#define W_OUT  (W_IN - KW + 1)   // 254
#define NW     (KH * KW * NF)    // 288

__global__ __launch_bounds__(256)
void dilation_kernel(const float* __restrict__ x,
                     const float* __restrict__ w,
                     float* __restrict__ out)
{
    __shared__ float ws[NW];   // 288 floats — MORE than blockDim, stride-load!

    const int tid = threadIdx.x;
    for (int i = tid; i < NW; i += 256) ws[i] = w[i];
    __syncthreads();

    const int pos   = tid >> 3;          // 0..31 : wo offset within tile
    const int fbase = (tid & 7) << 2;    // 0,4,...,28 : filter quad base

    const int wo = blockIdx.x * 32 + pos;
    const int ho = blockIdx.y;
    const int b  = blockIdx.z;
    if (wo >= W_OUT) return;

    // Load 9 weight quads into registers (LDS.128).
    float4 wv[9];
#pragma unroll
    for (int k = 0; k < 9; ++k)
        wv[k] = *reinterpret_cast<const float4*>(&ws[k * NF + fbase]);

    const float* xb = x + ((long long)(b * H_IN + ho) * W_IN + wo);

    // Load the 3x3 patch (broadcast across the 8 lanes of a position;
    // mostly L1/L2 hits — input is only 4 MB).
    float p[9];
#pragma unroll
    for (int i = 0; i < KH; ++i) {
#pragma unroll
        for (int j = 0; j < KW; ++j)
            p[i * KW + j] = xb[i * W_IN + j];
    }

    float4 acc;
    acc.x = p[0] + wv[0].x;
    acc.y = p[0] + wv[0].y;
    acc.z = p[0] + wv[0].z;
    acc.w = p[0] + wv[0].w;
#pragma unroll
    for (int k = 1; k < 9; ++k) {
        acc.x = fmaxf(acc.x, p[k] + wv[k].x);
        acc.y = fmaxf(acc.y, p[k] + wv[k].y);
        acc.z = fmaxf(acc.z, p[k] + wv[k].z);
        acc.w = fmaxf(acc.w, p[k] + wv[k].w);
    }

    long long oidx = (((long long)(b * H_OUT + ho)) * W_OUT + wo) * NF + fbase;
    *reinterpret_cast<float4*>(out + oidx) = acc;
}

extern "C" void kernel_launch(void* const* d_in, const int* in_sizes, int n_in,
                              void* d_out, int out_size)
{
    const float* x = (const float*)d_in[0];
    const float* w = (const float*)d_in[1];
    float* out = (float*)d_out;

    const int B = in_sizes[0] / (H_IN * W_IN);   // 16

    dim3 grid((W_OUT + 31) / 32, H_OUT, B);      // (8, 254, 16)
    dilation_kernel<<<grid, 256>>>(x, w, out);
}

// round 3
// speedup vs baseline: 1.1658x; 1.1658x over previous
#include <cuda_runtime.h>

// MorphologicalDilation: out[b,ho,wo,f] = max_{k} ( x[b, ho+ki, wo+kj, 0] + w[k, f] )
// x: (16,256,256,1) f32   w: (9,32) f32   out: (16,254,254,32) f32
//
// R3: sliding-window column kernel. Each thread owns (wo, filter-quad) and
// walks TILE_H output rows, keeping the 3x3 patch and all 9 weight quads in
// registers. Cuts L1 wavefronts/output from ~49 to ~9 (LDS amortized, 3 LDG
// instead of 9 per output).

#define H_IN   256
#define W_IN   256
#define KH     3
#define KW     3
#define NF     32
#define H_OUT  (H_IN - KH + 1)   // 254
#define W_OUT  (W_IN - KW + 1)   // 254
#define NW     (KH * KW * NF)    // 288
#define TILE_H 16

__device__ __forceinline__ float4 fq_max(float4 a, float4 b) {
    a.x = fmaxf(a.x, b.x); a.y = fmaxf(a.y, b.y);
    a.z = fmaxf(a.z, b.z); a.w = fmaxf(a.w, b.w);
    return a;
}
__device__ __forceinline__ float4 fq_adds(float s, float4 b) {
    float4 r; r.x = s + b.x; r.y = s + b.y; r.z = s + b.z; r.w = s + b.w;
    return r;
}

__global__ __launch_bounds__(256)
void dilation_kernel(const float* __restrict__ x,
                     const float* __restrict__ w,
                     float* __restrict__ out)
{
    __shared__ float ws[NW];
    const int tid = threadIdx.x;
    for (int i = tid; i < NW; i += 256) ws[i] = w[i];
    __syncthreads();

    const int pos   = tid >> 3;          // 0..31 : wo within tile
    const int fbase = (tid & 7) << 2;    // filter quad base

    const int wo  = blockIdx.x * 32 + pos;
    const int ho0 = blockIdx.y * TILE_H;
    const int b   = blockIdx.z;
    if (wo >= W_OUT) return;

    // 9 weight quads -> registers, read ONCE per TILE_H outputs.
    float4 wv[9];
#pragma unroll
    for (int k = 0; k < 9; ++k)
        wv[k] = *reinterpret_cast<const float4*>(&ws[k * NF + fbase]);

    const float* xb = x + ((long long)(b * H_IN + ho0) * W_IN + wo);

    // Prime first two patch rows.
    float r00 = xb[0],        r01 = xb[1],        r02 = xb[2];
    float r10 = xb[W_IN],     r11 = xb[W_IN + 1], r12 = xb[W_IN + 2];

    const int hend = min(TILE_H, H_OUT - ho0);
    float* op = out + (((long long)(b * H_OUT + ho0)) * W_OUT + wo) * NF + fbase;
    const long long ostride = (long long)W_OUT * NF;

    for (int s = 0; s < hend; ++s) {
        const float* xr = xb + (s + 2) * W_IN;
        float r20 = xr[0], r21 = xr[1], r22 = xr[2];

        float4 acc = fq_adds(r00, wv[0]);
        acc = fq_max(acc, fq_adds(r01, wv[1]));
        acc = fq_max(acc, fq_adds(r02, wv[2]));
        acc = fq_max(acc, fq_adds(r10, wv[3]));
        acc = fq_max(acc, fq_adds(r11, wv[4]));
        acc = fq_max(acc, fq_adds(r12, wv[5]));
        acc = fq_max(acc, fq_adds(r20, wv[6]));
        acc = fq_max(acc, fq_adds(r21, wv[7]));
        acc = fq_max(acc, fq_adds(r22, wv[8]));

        *reinterpret_cast<float4*>(op) = acc;
        op += ostride;

        // slide window down one row
        r00 = r10; r01 = r11; r02 = r12;
        r10 = r20; r11 = r21; r12 = r22;
    }
}

extern "C" void kernel_launch(void* const* d_in, const int* in_sizes, int n_in,
                              void* d_out, int out_size)
{
    const float* x = (const float*)d_in[0];
    const float* w = (const float*)d_in[1];
    float* out = (float*)d_out;

    const int B = in_sizes[0] / (H_IN * W_IN);   // 16

    dim3 grid((W_OUT + 31) / 32, (H_OUT + TILE_H - 1) / TILE_H, B); // (8,16,16)
    dilation_kernel<<<grid, 256>>>(x, w, out);
}

// round 4
// speedup vs baseline: 1.2781x; 1.0964x over previous
#include <cuda_runtime.h>

// MorphologicalDilation: out[b,ho,wo,f] = max_{k} ( x[b, ho+ki, wo+kj, 0] + w[k, f] )
// x: (16,256,256,1) f32   w: (9,32) f32   out: (16,254,254,32) f32
//
// R4: latency-oriented. Two output rows per loop iteration (2 independent
// accumulator trees), tree-shaped max reduction (depth 4 instead of 9),
// 32-bit indexing. All weights + sliding 4-row patch live in registers.

#define H_IN   256
#define W_IN   256
#define KH     3
#define KW     3
#define NF     32
#define H_OUT  (H_IN - KH + 1)   // 254
#define W_OUT  (W_IN - KW + 1)   // 254
#define NW     (KH * KW * NF)    // 288
#define TILE_H 16                // even; last tile = 14 rows (also even)

__device__ __forceinline__ float4 fq_max(float4 a, float4 b) {
    a.x = fmaxf(a.x, b.x); a.y = fmaxf(a.y, b.y);
    a.z = fmaxf(a.z, b.z); a.w = fmaxf(a.w, b.w);
    return a;
}
__device__ __forceinline__ float4 fq_adds(float s, float4 b) {
    float4 r; r.x = s + b.x; r.y = s + b.y; r.z = s + b.z; r.w = s + b.w;
    return r;
}

// 3x3 tropical conv with tree reduction: depth 4 instead of 9.
__device__ __forceinline__ float4 window_max(
    float a0, float a1, float a2,
    float b0, float b1, float b2,
    float c0, float c1, float c2,
    const float4* __restrict__ wv)
{
    float4 t0 = fq_max(fq_adds(a0, wv[0]), fq_adds(a1, wv[1]));
    float4 t1 = fq_max(fq_adds(a2, wv[2]), fq_adds(b0, wv[3]));
    float4 t2 = fq_max(fq_adds(b1, wv[4]), fq_adds(b2, wv[5]));
    float4 t3 = fq_max(fq_adds(c0, wv[6]), fq_adds(c1, wv[7]));
    float4 t4 = fq_adds(c2, wv[8]);
    return fq_max(fq_max(fq_max(t0, t1), fq_max(t2, t3)), t4);
}

__global__ __launch_bounds__(256)
void dilation_kernel(const float* __restrict__ x,
                     const float* __restrict__ w,
                     float* __restrict__ out)
{
    __shared__ float ws[NW];
    const int tid = threadIdx.x;
    for (int i = tid; i < NW; i += 256) ws[i] = w[i];
    __syncthreads();

    const int pos   = tid >> 3;          // 0..31 : wo within tile
    const int fbase = (tid & 7) << 2;    // filter quad base

    const int wo  = blockIdx.x * 32 + pos;
    const int ho0 = blockIdx.y * TILE_H;
    const int b   = blockIdx.z;
    if (wo >= W_OUT) return;

    // 9 weight quads in registers for the whole column.
    float4 wv[9];
#pragma unroll
    for (int k = 0; k < 9; ++k)
        wv[k] = *reinterpret_cast<const float4*>(&ws[k * NF + fbase]);

    // 32-bit indexing: max input idx ~1.05M, max output idx ~33M — both fit.
    const float* xb = x + (b * H_IN + ho0) * W_IN + wo;

    // Prime first two patch rows.
    float r00 = xb[0],    r01 = xb[1],        r02 = xb[2];
    float r10 = xb[W_IN], r11 = xb[W_IN + 1], r12 = xb[W_IN + 2];

    const int hend = min(TILE_H, H_OUT - ho0);   // 16 or 14 — always even
    float* op = out + ((b * H_OUT + ho0) * W_OUT + wo) * NF + fbase;
    const int ostride = W_OUT * NF;

#pragma unroll 2
    for (int s = 0; s < hend; s += 2) {
        const float* xr2 = xb + (s + 2) * W_IN;
        const float* xr3 = xr2 + W_IN;
        // Issue all 6 loads up front.
        float r20 = xr2[0], r21 = xr2[1], r22 = xr2[2];
        float r30 = xr3[0], r31 = xr3[1], r32 = xr3[2];

        // Two independent reduction trees.
        float4 acc0 = window_max(r00, r01, r02, r10, r11, r12, r20, r21, r22, wv);
        float4 acc1 = window_max(r10, r11, r12, r20, r21, r22, r30, r31, r32, wv);

        *reinterpret_cast<float4*>(op)           = acc0;
        *reinterpret_cast<float4*>(op + ostride) = acc1;
        op += 2 * ostride;

        // Slide window down two rows.
        r00 = r20; r01 = r21; r02 = r22;
        r10 = r30; r11 = r31; r12 = r32;
    }
}

extern "C" void kernel_launch(void* const* d_in, const int* in_sizes, int n_in,
                              void* d_out, int out_size)
{
    const float* x = (const float*)d_in[0];
    const float* w = (const float*)d_in[1];
    float* out = (float*)d_out;

    const int B = in_sizes[0] / (H_IN * W_IN);   // 16

    dim3 grid((W_OUT + 31) / 32, (H_OUT + TILE_H - 1) / TILE_H, B); // (8,16,16)
    dilation_kernel<<<grid, 256>>>(x, w, out);
}

// round 5
// speedup vs baseline: 1.4872x; 1.1635x over previous
#include <cuda_runtime.h>

// MorphologicalDilation: out[b,ho,wo,f] = max_{k} ( x[b, ho+ki, wo+kj, 0] + w[k, f] )
// x: (16,256,256,1) f32   w: (9,32) f32   out: (16,254,254,32) f32
//
// R5: latency-focused. Software-pipelined input loads (prefetch distance =
// one full iteration), 128-thread CTAs for better regfile quantization,
// 2 output rows per iteration with tree-shaped max reduction.

#define H_IN   256
#define W_IN   256
#define NF     32
#define H_OUT  254
#define W_OUT  254
#define NW     288
#define TILE_H 16
#define TILE_W 16   // wo positions per block (128 threads / 8 filter-lanes)

__device__ __forceinline__ float4 fq_max(float4 a, float4 b) {
    a.x = fmaxf(a.x, b.x); a.y = fmaxf(a.y, b.y);
    a.z = fmaxf(a.z, b.z); a.w = fmaxf(a.w, b.w);
    return a;
}
__device__ __forceinline__ float4 fq_adds(float s, float4 b) {
    float4 r; r.x = s + b.x; r.y = s + b.y; r.z = s + b.z; r.w = s + b.w;
    return r;
}

// 3x3 tropical conv, tree reduction (depth 4).
__device__ __forceinline__ float4 window_max(
    float a0, float a1, float a2,
    float b0, float b1, float b2,
    float c0, float c1, float c2,
    const float4* __restrict__ wv)
{
    float4 t0 = fq_max(fq_adds(a0, wv[0]), fq_adds(a1, wv[1]));
    float4 t1 = fq_max(fq_adds(a2, wv[2]), fq_adds(b0, wv[3]));
    float4 t2 = fq_max(fq_adds(b1, wv[4]), fq_adds(b2, wv[5]));
    float4 t3 = fq_max(fq_adds(c0, wv[6]), fq_adds(c1, wv[7]));
    float4 t4 = fq_adds(c2, wv[8]);
    return fq_max(fq_max(fq_max(t0, t1), fq_max(t2, t3)), t4);
}

__global__ __launch_bounds__(128)
void dilation_kernel(const float* __restrict__ x,
                     const float* __restrict__ w,
                     float* __restrict__ out)
{
    __shared__ float ws[NW];
    const int tid = threadIdx.x;
    for (int i = tid; i < NW; i += 128) ws[i] = w[i];
    __syncthreads();

    const int pos   = tid >> 3;          // 0..15 : wo within tile
    const int fbase = (tid & 7) << 2;    // filter quad base

    const int wo  = blockIdx.x * TILE_W + pos;
    const int ho0 = blockIdx.y * TILE_H;
    const int b   = blockIdx.z;
    if (wo >= W_OUT) return;

    float4 wv[9];
#pragma unroll
    for (int k = 0; k < 9; ++k)
        wv[k] = *reinterpret_cast<const float4*>(&ws[k * NF + fbase]);

    const float* xb = x + (b * H_IN + ho0) * W_IN + wo;

    // Prime 4 window rows (rows ho0 .. ho0+3, always in-bounds: ho0+3 <= 243).
    float a0 = xb[0],        a1 = xb[1],            a2 = xb[2];
    float b0 = xb[W_IN],     b1 = xb[W_IN + 1],     b2 = xb[W_IN + 2];
    float c0 = xb[2 * W_IN], c1 = xb[2 * W_IN + 1], c2 = xb[2 * W_IN + 2];
    float d0 = xb[3 * W_IN], d1 = xb[3 * W_IN + 1], d2 = xb[3 * W_IN + 2];

    const int hend = min(TILE_H, H_OUT - ho0);   // 16 or 14 (even)
    const int rmax = (H_IN - 1) - ho0;           // last valid relative row
    float* op = out + ((b * H_OUT + ho0) * W_OUT + wo) * NF + fbase;
    const int ostride = W_OUT * NF;

#pragma unroll 2
    for (int s = 0; s < hend; s += 2) {
        // Prefetch rows s+4, s+5 for the NEXT iteration (row-clamped so the
        // final iterations read valid-but-unused data instead of OOB).
        const int r4 = min(s + 4, rmax);
        const int r5 = min(s + 5, rmax);
        const float* x4 = xb + r4 * W_IN;
        const float* x5 = xb + r5 * W_IN;
        float e0 = x4[0], e1 = x4[1], e2 = x4[2];
        float f0 = x5[0], f1 = x5[1], f2 = x5[2];

        // Compute from rows loaded >= 1 iteration ago.
        float4 acc0 = window_max(a0, a1, a2, b0, b1, b2, c0, c1, c2, wv);
        float4 acc1 = window_max(b0, b1, b2, c0, c1, c2, d0, d1, d2, wv);

        *reinterpret_cast<float4*>(op)           = acc0;
        *reinterpret_cast<float4*>(op + ostride) = acc1;
        op += 2 * ostride;

        // Slide window down two rows; retire prefetched rows into the window.
        a0 = c0; a1 = c1; a2 = c2;
        b0 = d0; b1 = d1; b2 = d2;
        c0 = e0; c1 = e1; c2 = e2;
        d0 = f0; d1 = f1; d2 = f2;
    }
}

extern "C" void kernel_launch(void* const* d_in, const int* in_sizes, int n_in,
                              void* d_out, int out_size)
{
    const float* x = (const float*)d_in[0];
    const float* w = (const float*)d_in[1];
    float* out = (float*)d_out;

    const int B = in_sizes[0] / (H_IN * W_IN);   // 16

    dim3 grid((W_OUT + TILE_W - 1) / TILE_W,
              (H_OUT + TILE_H - 1) / TILE_H, B);   // (16, 16, 16) = 4096 CTAs
    dilation_kernel<<<grid, 128>>>(x, w, out);
}

// round 7
// speedup vs baseline: 1.9046x; 1.2807x over previous
#include <cuda_runtime.h>

// MorphologicalDilation: out[b,ho,wo,f] = max_{k} ( x[b, ho+ki, wo+kj, 0] + w[k, f] )
// x: (16,256,256,1) f32   w: (9,32) f32   out: (16,254,254,32) f32
//
// R7: packed add.rn.f32x2 (exists on sm_100+; max.f32x2 does NOT), scalar
// FMNMX trees on renamed halves, fully-unrolled 16-row column per thread
// (no slide MOVs, no loop IMADs — all addresses are [reg+imm]).

#define H_IN   256
#define W_IN   256
#define NF     32
#define H_OUT  254
#define W_OUT  254
#define NW     288
#define TILE_H 16
#define TILE_W 16
#define OSTRIDE (W_OUT * NF)   // 8128 floats between output rows

typedef unsigned long long u64;

__device__ __forceinline__ u64 padd(u64 a, u64 b) {
    u64 d; asm("add.rn.f32x2 %0, %1, %2;" : "=l"(d) : "l"(a), "l"(b)); return d;
}
__device__ __forceinline__ u64 pdup(float x) {
    u64 d; asm("mov.b64 %0, {%1, %1};" : "=l"(d) : "f"(x)); return d;
}
__device__ __forceinline__ void punpack(float& lo, float& hi, u64 d) {
    asm("mov.b64 {%0, %1}, %2;" : "=f"(lo), "=f"(hi) : "l"(d));
}

// 2 packed filters over one 3x3 window: 9 packed adds, then two scalar
// tree-max reductions (depth 4) on the unpacked halves.
__device__ __forceinline__ void win_half(
    float& out_lo, float& out_hi,
    const u64* a, const u64* b, const u64* c,   // 3 window rows, dup-packed
    const u64* wh)                              // 9 packed weight pairs
{
    float lo[9], hi[9];
    punpack(lo[0], hi[0], padd(a[0], wh[0]));
    punpack(lo[1], hi[1], padd(a[1], wh[1]));
    punpack(lo[2], hi[2], padd(a[2], wh[2]));
    punpack(lo[3], hi[3], padd(b[0], wh[3]));
    punpack(lo[4], hi[4], padd(b[1], wh[4]));
    punpack(lo[5], hi[5], padd(b[2], wh[5]));
    punpack(lo[6], hi[6], padd(c[0], wh[6]));
    punpack(lo[7], hi[7], padd(c[1], wh[7]));
    punpack(lo[8], hi[8], padd(c[2], wh[8]));

    float t0 = fmaxf(fmaxf(lo[0], lo[1]), fmaxf(lo[2], lo[3]));
    float t1 = fmaxf(fmaxf(lo[4], lo[5]), fmaxf(lo[6], lo[7]));
    out_lo = fmaxf(fmaxf(t0, t1), lo[8]);

    float u0 = fmaxf(fmaxf(hi[0], hi[1]), fmaxf(hi[2], hi[3]));
    float u1 = fmaxf(fmaxf(hi[4], hi[5]), fmaxf(hi[6], hi[7]));
    out_hi = fmaxf(fmaxf(u0, u1), hi[8]);
}

template<int NR>
__device__ __forceinline__ void do_column(
    const float* __restrict__ xb, float* __restrict__ op,
    const u64* wlo, const u64* whi)
{
    u64 p[3][3];   // rotating 3-row window; all indices constant after unroll
    p[0][0] = pdup(xb[0]);
    p[0][1] = pdup(xb[1]);
    p[0][2] = pdup(xb[2]);
    p[1][0] = pdup(xb[W_IN]);
    p[1][1] = pdup(xb[W_IN + 1]);
    p[1][2] = pdup(xb[W_IN + 2]);

#pragma unroll
    for (int s = 0; s < NR; ++s) {
        const float* xr = xb + (s + 2) * W_IN;
        const int c = (s + 2) % 3;
        p[c][0] = pdup(xr[0]);
        p[c][1] = pdup(xr[1]);
        p[c][2] = pdup(xr[2]);

        const int r0 = s % 3, r1 = (s + 1) % 3;
        float4 acc;
        win_half(acc.x, acc.y, p[r0], p[r1], p[c], wlo);
        win_half(acc.z, acc.w, p[r0], p[r1], p[c], whi);

        *reinterpret_cast<float4*>(op + s * OSTRIDE) = acc;
    }
}

__global__ __launch_bounds__(128, 6)
void dilation_kernel(const float* __restrict__ x,
                     const float* __restrict__ w,
                     float* __restrict__ out)
{
    __shared__ float ws[NW];
    const int tid = threadIdx.x;
    for (int i = tid; i < NW; i += 128) ws[i] = w[i];
    __syncthreads();

    const int pos   = tid >> 3;          // 0..15 : wo within tile
    const int fbase = (tid & 7) << 2;    // filter quad base

    const int wo  = blockIdx.x * TILE_W + pos;
    const int ho0 = blockIdx.y * TILE_H;
    const int b   = blockIdx.z;
    if (wo >= W_OUT) return;

    // 9 packed weight pairs per half: wlo = filters (f,f+1), whi = (f+2,f+3).
    u64 wlo[9], whi[9];
#pragma unroll
    for (int k = 0; k < 9; ++k) {
        ulonglong2 q = *reinterpret_cast<const ulonglong2*>(&ws[k * NF + fbase]);
        wlo[k] = q.x; whi[k] = q.y;
    }

    const float* xb = x + (b * H_IN + ho0) * W_IN + wo;
    float* op = out + ((b * H_OUT + ho0) * W_OUT + wo) * NF + fbase;

    if (ho0 + TILE_H <= H_OUT) {
        do_column<TILE_H>(xb, op, wlo, whi);       // 16 rows (15 of 16 tiles)
    } else {
        do_column<H_OUT % TILE_H>(xb, op, wlo, whi); // last tile: 14 rows
    }
}

extern "C" void kernel_launch(void* const* d_in, const int* in_sizes, int n_in,
                              void* d_out, int out_size)
{
    const float* x = (const float*)d_in[0];
    const float* w = (const float*)d_in[1];
    float* out = (float*)d_out;

    const int B = in_sizes[0] / (H_IN * W_IN);   // 16

    dim3 grid((W_OUT + TILE_W - 1) / TILE_W,
              (H_OUT + TILE_H - 1) / TILE_H, B);   // (16,16,16)
    dilation_kernel<<<grid, 128>>>(x, w, out);
}